// round 4
// baseline (speedup 1.0000x reference)
#include <cuda_runtime.h>
#include <float.h>

// Problem shape (fixed by the reference)
#define NB 32
#define NT 2048
#define ND 512

#define NC 8                 // chunks (blocks) per batch
#define NW 8                 // warps per block
#define ROWS (NT / NC)       // 256 rows per block
#define RPW (ROWS / NW)      // 32 rows per warp

// Scratch (no cudaMalloc allowed)
__device__ __align__(16) float g_s_part[NB * NC * ND];           // 512 KB
__device__ float g_pm[NB * NC];
__device__ float g_pl[NB * NC];
__device__ __align__(16) float g_pacc[(size_t)NB * NC * ND];     // 512 KB
__device__ int g_cnt_s[NB];   // zero-init; reset by last block each launch
__device__ int g_cnt_p[NB];

__device__ __forceinline__ void f4add(float4& a, const float4 b) {
    a.x += b.x; a.y += b.y; a.z += b.z; a.w += b.w;
}

// ---------------------------------------------------------------------------
// Fully fused, 3 blocks/SM (reg-capped): per-block column sum -> per-batch
// inter-block barrier -> s fold into SMEM -> online-softmax pooling (reverse
// row order for L2 reuse, s read from SMEM to keep regs low) -> in-block
// merge -> last block per batch combines and writes output. Fixed fold
// orders everywhere -> bit-deterministic.
// ---------------------------------------------------------------------------
__global__ void __launch_bounds__(256, 3)
k_fused(const float* __restrict__ x, float* __restrict__ out) {
    const int b = blockIdx.x, c = blockIdx.y;
    const int tid = threadIdx.x, w = tid >> 5, lane = tid & 31;

    __shared__ float sm_m[NW], sm_l[NW];
    __shared__ int sm_last;
    __shared__ __align__(16) float sm_s[ND];          // 2 KB
    __shared__ __align__(16) float sm_acc[NW][ND];    // 16 KB, reused twice

    const float4* xb = (const float4*)(x + (size_t)b * NT * ND);
    const int tbase = c * ROWS + w;                   // rows: tbase + j*NW

    // ---- Phase 1: column-sum of this block's 256 rows, batched loads ----
    float4 q0 = {0.f, 0.f, 0.f, 0.f}, q1 = q0, q2 = q0, q3 = q0;
    for (int j = 0; j < RPW; j += 2) {
        const float4* rA = xb + (size_t)(tbase + j * NW) * (ND / 4);
        const float4* rB = xb + (size_t)(tbase + (j + 1) * NW) * (ND / 4);
        const float4 a0 = rA[lane],      a1 = rA[32 + lane];
        const float4 a2 = rA[64 + lane], a3 = rA[96 + lane];
        const float4 b0 = rB[lane],      b1 = rB[32 + lane];
        const float4 b2 = rB[64 + lane], b3 = rB[96 + lane];
        f4add(q0, a0); f4add(q1, a1); f4add(q2, a2); f4add(q3, a3);
        f4add(q0, b0); f4add(q1, b1); f4add(q2, b2); f4add(q3, b3);
    }
    {
        float4* sa = (float4*)sm_acc[w];
        sa[lane] = q0; sa[32 + lane] = q1; sa[64 + lane] = q2; sa[96 + lane] = q3;
    }
    __syncthreads();
    if (tid < ND / 4) {
        float4 s = {0.f, 0.f, 0.f, 0.f};
        #pragma unroll
        for (int p = 0; p < NW; ++p) f4add(s, ((const float4*)sm_acc[p])[tid]);
        ((float4*)(g_s_part + (size_t)(b * NC + c) * ND))[tid] = s;
    }
    __threadfence();
    __syncthreads();

    // ---- Per-batch inter-block barrier (all blocks co-resident) ----
    if (tid == 0) {
        atomicAdd(&g_cnt_s[b], 1);
        while (atomicAdd(&g_cnt_s[b], 0) < NC) __nanosleep(128);
    }
    __syncthreads();
    __threadfence();

    // ---- Fold the 8 partials (fixed order) -> s in SMEM ----
    if (tid < ND / 4) {
        const float4* sp = (const float4*)(g_s_part + (size_t)b * NC * ND);
        float4 s = {0.f, 0.f, 0.f, 0.f};
        #pragma unroll
        for (int p = 0; p < NC; ++p) f4add(s, sp[p * (ND / 4) + tid]);
        ((float4*)sm_s)[tid] = s;
    }
    __syncthreads();
    const float4* sS = (const float4*)sm_s;

    // ---- Phase 2: online-softmax pooling, reverse row order (L2-hot) ----
    float m = -FLT_MAX, l = 0.f;
    float4 a0 = {0.f, 0.f, 0.f, 0.f}, a1 = a0, a2 = a0, a3 = a0;

    for (int j = RPW - 1; j >= 0; --j) {
        const float4* row = xb + (size_t)(tbase + j * NW) * (ND / 4);
        const float4 v0 = row[lane];
        const float4 v1 = row[32 + lane];
        const float4 v2 = row[64 + lane];
        const float4 v3 = row[96 + lane];
        const float4 s0 = sS[lane];
        const float4 s1 = sS[32 + lane];
        const float4 s2 = sS[64 + lane];
        const float4 s3 = sS[96 + lane];

        // per-lane partial of w = sum_d x*(s - x); 4 independent chains
        float r0 = 0.f, r1 = 0.f, r2 = 0.f, r3 = 0.f;
        r0 = fmaf(v0.x, s0.x - v0.x, r0); r1 = fmaf(v0.y, s0.y - v0.y, r1);
        r2 = fmaf(v0.z, s0.z - v0.z, r2); r3 = fmaf(v0.w, s0.w - v0.w, r3);
        r0 = fmaf(v1.x, s1.x - v1.x, r0); r1 = fmaf(v1.y, s1.y - v1.y, r1);
        r2 = fmaf(v1.z, s1.z - v1.z, r2); r3 = fmaf(v1.w, s1.w - v1.w, r3);
        r0 = fmaf(v2.x, s2.x - v2.x, r0); r1 = fmaf(v2.y, s2.y - v2.y, r1);
        r2 = fmaf(v2.z, s2.z - v2.z, r2); r3 = fmaf(v2.w, s2.w - v2.w, r3);
        r0 = fmaf(v3.x, s3.x - v3.x, r0); r1 = fmaf(v3.y, s3.y - v3.y, r1);
        r2 = fmaf(v3.z, s3.z - v3.z, r2); r3 = fmaf(v3.w, s3.w - v3.w, r3);
        float r = (r0 + r1) + (r2 + r3);

        #pragma unroll
        for (int o = 16; o; o >>= 1)
            r += __shfl_xor_sync(0xffffffffu, r, o);

        if (r > m) {                       // warp-uniform; p = 1
            const float sc = __expf(m - r);
            l = fmaf(l, sc, 1.f);
            a0.x = fmaf(a0.x, sc, v0.x); a0.y = fmaf(a0.y, sc, v0.y);
            a0.z = fmaf(a0.z, sc, v0.z); a0.w = fmaf(a0.w, sc, v0.w);
            a1.x = fmaf(a1.x, sc, v1.x); a1.y = fmaf(a1.y, sc, v1.y);
            a1.z = fmaf(a1.z, sc, v1.z); a1.w = fmaf(a1.w, sc, v1.w);
            a2.x = fmaf(a2.x, sc, v2.x); a2.y = fmaf(a2.y, sc, v2.y);
            a2.z = fmaf(a2.z, sc, v2.z); a2.w = fmaf(a2.w, sc, v2.w);
            a3.x = fmaf(a3.x, sc, v3.x); a3.y = fmaf(a3.y, sc, v3.y);
            a3.z = fmaf(a3.z, sc, v3.z); a3.w = fmaf(a3.w, sc, v3.w);
            m = r;
        } else {                           // common path: no rescale
            const float p = __expf(r - m);
            l += p;
            a0.x = fmaf(p, v0.x, a0.x); a0.y = fmaf(p, v0.y, a0.y);
            a0.z = fmaf(p, v0.z, a0.z); a0.w = fmaf(p, v0.w, a0.w);
            a1.x = fmaf(p, v1.x, a1.x); a1.y = fmaf(p, v1.y, a1.y);
            a1.z = fmaf(p, v1.z, a1.z); a1.w = fmaf(p, v1.w, a1.w);
            a2.x = fmaf(p, v2.x, a2.x); a2.y = fmaf(p, v2.y, a2.y);
            a2.z = fmaf(p, v2.z, a2.z); a2.w = fmaf(p, v2.w, a2.w);
            a3.x = fmaf(p, v3.x, a3.x); a3.y = fmaf(p, v3.y, a3.y);
            a3.z = fmaf(p, v3.z, a3.z); a3.w = fmaf(p, v3.w, a3.w);
        }
    }

    // ---- In-block merge of 8 warp partials (fixed order) ----
    __syncthreads();                       // sm_acc reuse guard
    if (lane == 0) { sm_m[w] = m; sm_l[w] = l; }
    {
        float4* sa = (float4*)sm_acc[w];
        sa[lane] = a0; sa[32 + lane] = a1; sa[64 + lane] = a2; sa[96 + lane] = a3;
    }
    __syncthreads();
    if (tid < ND / 4) {
        float M = -FLT_MAX;
        #pragma unroll
        for (int p = 0; p < NW; ++p) M = fmaxf(M, sm_m[p]);
        float L = 0.f;
        float4 o = {0.f, 0.f, 0.f, 0.f};
        #pragma unroll
        for (int p = 0; p < NW; ++p) {
            const float e = __expf(sm_m[p] - M);
            L = fmaf(sm_l[p], e, L);
            const float4 a = ((const float4*)sm_acc[p])[tid];
            o.x = fmaf(e, a.x, o.x); o.y = fmaf(e, a.y, o.y);
            o.z = fmaf(e, a.z, o.z); o.w = fmaf(e, a.w, o.w);
        }
        const int pi = b * NC + c;
        if (tid == 0) { g_pm[pi] = M; g_pl[pi] = L; }
        ((float4*)(g_pacc + (size_t)pi * ND))[tid] = o;
    }
    __threadfence();
    __syncthreads();

    // ---- Last block per batch combines and writes output ----
    if (tid == 0) {
        const int old = atomicAdd(&g_cnt_p[b], 1);
        sm_last = (old == NC - 1);
    }
    __syncthreads();
    if (sm_last) {
        __threadfence();
        if (tid < ND / 4) {
            const float* pm = g_pm + b * NC;
            const float* pl = g_pl + b * NC;
            float M = -FLT_MAX;
            #pragma unroll
            for (int p = 0; p < NC; ++p) M = fmaxf(M, pm[p]);
            float L = 0.f;
            float4 o = {0.f, 0.f, 0.f, 0.f};
            #pragma unroll
            for (int p = 0; p < NC; ++p) {
                const float e = __expf(pm[p] - M);
                L = fmaf(pl[p], e, L);
                const float4 a =
                    ((const float4*)(g_pacc + (size_t)(b * NC + p) * ND))[tid];
                o.x = fmaf(e, a.x, o.x); o.y = fmaf(e, a.y, o.y);
                o.z = fmaf(e, a.z, o.z); o.w = fmaf(e, a.w, o.w);
            }
            const float inv = 1.f / L;
            o.x *= inv; o.y *= inv; o.z *= inv; o.w *= inv;
            ((float4*)(out + (size_t)b * ND))[tid] = o;
        }
        // reset counters for the next graph replay
        if (tid == 0) {
            atomicExch(&g_cnt_s[b], 0);
            atomicExch(&g_cnt_p[b], 0);
        }
    }
}

// ---------------------------------------------------------------------------
extern "C" void kernel_launch(void* const* d_in, const int* in_sizes, int n_in,
                              void* d_out, int out_size) {
    (void)in_sizes; (void)n_in; (void)out_size;
    const float* x = (const float*)d_in[0];
    float* out = (float*)d_out;

    k_fused<<<dim3(NB, NC), 256>>>(x, out);
}

// round 5
// speedup vs baseline: 1.0567x; 1.0567x over previous
#include <cuda_runtime.h>
#include <float.h>

// Problem shape (fixed by the reference)
#define NB 32
#define NT 2048
#define ND 512

#define NC 8                  // chunks (blocks) per batch -> grid (32,8)=256
#define NW 16                 // warps per block (512 threads)
#define ROWS (NT / NC)        // 256 rows per block
#define RPW (ROWS / NW)       // 16 rows per warp  -> 4096 warps total

// Scratch (no cudaMalloc allowed)
__device__ __align__(16) float g_s_part[NB * NC * ND];           // 512 KB
__device__ float g_pm[NB * NC];
__device__ float g_pl[NB * NC];
__device__ __align__(16) float g_pacc[(size_t)NB * NC * ND];     // 512 KB
__device__ int g_cnt_s[NB];   // zero-init; reset by last block each launch
__device__ int g_cnt_p[NB];

__device__ __forceinline__ void f4add(float4& a, const float4 b) {
    a.x += b.x; a.y += b.y; a.z += b.z; a.w += b.w;
}

// ---------------------------------------------------------------------------
// Fully fused, 512 threads/block, 2 blocks/SM guaranteed (launch_bounds) so
// the per-batch spin barrier is deadlock-free (256 blocks <= 296 slots).
// Softmax accumulators live in SMEM (warp-private slices) to fit 64 regs.
// All fold orders fixed -> bit-deterministic.
// ---------------------------------------------------------------------------
__global__ void __launch_bounds__(512, 2)
k_fused(const float* __restrict__ x, float* __restrict__ out) {
    const int b = blockIdx.x, c = blockIdx.y;
    const int tid = threadIdx.x, w = tid >> 5, lane = tid & 31;

    __shared__ float sm_m[NW], sm_l[NW];
    __shared__ int sm_last;
    __shared__ __align__(16) float sm_s[ND];          // 2 KB
    __shared__ __align__(16) float sm_acc[NW][ND];    // 32 KB, reused twice

    const float4* xb = (const float4*)(x + (size_t)b * NT * ND);
    const int tbase = c * ROWS + w;                   // rows: tbase + j*NW

    // ---- Phase 1: column-sum of this block's 256 rows ----
    float4 q0 = {0.f, 0.f, 0.f, 0.f}, q1 = q0, q2 = q0, q3 = q0;
    #pragma unroll 2
    for (int j = 0; j < RPW; ++j) {
        const float4* row = xb + (size_t)(tbase + j * NW) * (ND / 4);
        const float4 v0 = row[lane],      v1 = row[32 + lane];
        const float4 v2 = row[64 + lane], v3 = row[96 + lane];
        f4add(q0, v0); f4add(q1, v1); f4add(q2, v2); f4add(q3, v3);
    }
    {
        float4* sa = (float4*)sm_acc[w];
        sa[lane] = q0; sa[32 + lane] = q1; sa[64 + lane] = q2; sa[96 + lane] = q3;
    }
    __syncthreads();
    if (tid < ND / 4) {
        float4 s = {0.f, 0.f, 0.f, 0.f};
        #pragma unroll
        for (int p = 0; p < NW; ++p) f4add(s, ((const float4*)sm_acc[p])[tid]);
        ((float4*)(g_s_part + (size_t)(b * NC + c) * ND))[tid] = s;
    }
    __threadfence();
    __syncthreads();

    // ---- Per-batch inter-block barrier (all blocks co-resident) ----
    if (tid == 0) {
        atomicAdd(&g_cnt_s[b], 1);
        while (atomicAdd(&g_cnt_s[b], 0) < NC) __nanosleep(128);
    }
    __syncthreads();
    __threadfence();

    // ---- Zero warp accumulators; fold the 8 s-partials -> sm_s ----
    {
        float4 z = {0.f, 0.f, 0.f, 0.f};
        float4* sa = (float4*)sm_acc[w];
        sa[lane] = z; sa[32 + lane] = z; sa[64 + lane] = z; sa[96 + lane] = z;
    }
    if (tid < ND / 4) {
        const float4* sp = (const float4*)(g_s_part + (size_t)b * NC * ND);
        float4 s = {0.f, 0.f, 0.f, 0.f};
        #pragma unroll
        for (int p = 0; p < NC; ++p) f4add(s, sp[p * (ND / 4) + tid]);
        ((float4*)sm_s)[tid] = s;
    }
    __syncthreads();
    const float4* sS = (const float4*)sm_s;
    float4* const myacc = (float4*)sm_acc[w];   // warp-private, no sync needed

    // ---- Phase 2: online-softmax pooling, reverse row order (L2-hot) ----
    float m = -FLT_MAX, l = 0.f;

    for (int j = RPW - 1; j >= 0; --j) {
        const float4* row = xb + (size_t)(tbase + j * NW) * (ND / 4);
        const float4 v0 = row[lane];
        const float4 v1 = row[32 + lane];
        const float4 v2 = row[64 + lane];
        const float4 v3 = row[96 + lane];

        // per-lane partial of w = sum_d x*(s - x); 4 independent chains
        float r0, r1, r2, r3;
        {
            const float4 s0 = sS[lane];
            r0 = v0.x * (s0.x - v0.x); r1 = v0.y * (s0.y - v0.y);
            r2 = v0.z * (s0.z - v0.z); r3 = v0.w * (s0.w - v0.w);
        }
        {
            const float4 s1 = sS[32 + lane];
            r0 = fmaf(v1.x, s1.x - v1.x, r0); r1 = fmaf(v1.y, s1.y - v1.y, r1);
            r2 = fmaf(v1.z, s1.z - v1.z, r2); r3 = fmaf(v1.w, s1.w - v1.w, r3);
        }
        {
            const float4 s2 = sS[64 + lane];
            r0 = fmaf(v2.x, s2.x - v2.x, r0); r1 = fmaf(v2.y, s2.y - v2.y, r1);
            r2 = fmaf(v2.z, s2.z - v2.z, r2); r3 = fmaf(v2.w, s2.w - v2.w, r3);
        }
        {
            const float4 s3 = sS[96 + lane];
            r0 = fmaf(v3.x, s3.x - v3.x, r0); r1 = fmaf(v3.y, s3.y - v3.y, r1);
            r2 = fmaf(v3.z, s3.z - v3.z, r2); r3 = fmaf(v3.w, s3.w - v3.w, r3);
        }
        float r = (r0 + r1) + (r2 + r3);

        #pragma unroll
        for (int o = 16; o; o >>= 1)
            r += __shfl_xor_sync(0xffffffffu, r, o);

        if (r > m) {                       // warp-uniform; p = 1
            const float sc = __expf(m - r);
            l = fmaf(l, sc, 1.f);
            float4 A;
            A = myacc[lane];
            A.x = fmaf(A.x, sc, v0.x); A.y = fmaf(A.y, sc, v0.y);
            A.z = fmaf(A.z, sc, v0.z); A.w = fmaf(A.w, sc, v0.w);
            myacc[lane] = A;
            A = myacc[32 + lane];
            A.x = fmaf(A.x, sc, v1.x); A.y = fmaf(A.y, sc, v1.y);
            A.z = fmaf(A.z, sc, v1.z); A.w = fmaf(A.w, sc, v1.w);
            myacc[32 + lane] = A;
            A = myacc[64 + lane];
            A.x = fmaf(A.x, sc, v2.x); A.y = fmaf(A.y, sc, v2.y);
            A.z = fmaf(A.z, sc, v2.z); A.w = fmaf(A.w, sc, v2.w);
            myacc[64 + lane] = A;
            A = myacc[96 + lane];
            A.x = fmaf(A.x, sc, v3.x); A.y = fmaf(A.y, sc, v3.y);
            A.z = fmaf(A.z, sc, v3.z); A.w = fmaf(A.w, sc, v3.w);
            myacc[96 + lane] = A;
            m = r;
        } else {                           // common path: acc += p*v
            const float p = __expf(r - m);
            l += p;
            float4 A;
            A = myacc[lane];
            A.x = fmaf(p, v0.x, A.x); A.y = fmaf(p, v0.y, A.y);
            A.z = fmaf(p, v0.z, A.z); A.w = fmaf(p, v0.w, A.w);
            myacc[lane] = A;
            A = myacc[32 + lane];
            A.x = fmaf(p, v1.x, A.x); A.y = fmaf(p, v1.y, A.y);
            A.z = fmaf(p, v1.z, A.z); A.w = fmaf(p, v1.w, A.w);
            myacc[32 + lane] = A;
            A = myacc[64 + lane];
            A.x = fmaf(p, v2.x, A.x); A.y = fmaf(p, v2.y, A.y);
            A.z = fmaf(p, v2.z, A.z); A.w = fmaf(p, v2.w, A.w);
            myacc[64 + lane] = A;
            A = myacc[96 + lane];
            A.x = fmaf(p, v3.x, A.x); A.y = fmaf(p, v3.y, A.y);
            A.z = fmaf(p, v3.z, A.z); A.w = fmaf(p, v3.w, A.w);
            myacc[96 + lane] = A;
        }
    }

    // ---- In-block merge of 16 warp partials (already in sm_acc) ----
    if (lane == 0) { sm_m[w] = m; sm_l[w] = l; }
    __syncthreads();
    if (tid < ND / 4) {
        float M = -FLT_MAX;
        #pragma unroll
        for (int p = 0; p < NW; ++p) M = fmaxf(M, sm_m[p]);
        float L = 0.f;
        float4 o = {0.f, 0.f, 0.f, 0.f};
        #pragma unroll
        for (int p = 0; p < NW; ++p) {
            const float e = __expf(sm_m[p] - M);
            L = fmaf(sm_l[p], e, L);
            const float4 a = ((const float4*)sm_acc[p])[tid];
            o.x = fmaf(e, a.x, o.x); o.y = fmaf(e, a.y, o.y);
            o.z = fmaf(e, a.z, o.z); o.w = fmaf(e, a.w, o.w);
        }
        const int pi = b * NC + c;
        if (tid == 0) { g_pm[pi] = M; g_pl[pi] = L; }
        ((float4*)(g_pacc + (size_t)pi * ND))[tid] = o;
    }
    __threadfence();
    __syncthreads();

    // ---- Last block per batch combines and writes output ----
    if (tid == 0) {
        const int old = atomicAdd(&g_cnt_p[b], 1);
        sm_last = (old == NC - 1);
    }
    __syncthreads();
    if (sm_last) {
        __threadfence();
        if (tid < ND / 4) {
            const float* pm = g_pm + b * NC;
            const float* pl = g_pl + b * NC;
            float M = -FLT_MAX;
            #pragma unroll
            for (int p = 0; p < NC; ++p) M = fmaxf(M, pm[p]);
            float L = 0.f;
            float4 o = {0.f, 0.f, 0.f, 0.f};
            #pragma unroll
            for (int p = 0; p < NC; ++p) {
                const float e = __expf(pm[p] - M);
                L = fmaf(pl[p], e, L);
                const float4 a =
                    ((const float4*)(g_pacc + (size_t)(b * NC + p) * ND))[tid];
                o.x = fmaf(e, a.x, o.x); o.y = fmaf(e, a.y, o.y);
                o.z = fmaf(e, a.z, o.z); o.w = fmaf(e, a.w, o.w);
            }
            const float inv = 1.f / L;
            o.x *= inv; o.y *= inv; o.z *= inv; o.w *= inv;
            ((float4*)(out + (size_t)b * ND))[tid] = o;
        }
        // reset counters for the next graph replay
        if (tid == 0) {
            atomicExch(&g_cnt_s[b], 0);
            atomicExch(&g_cnt_p[b], 0);
        }
    }
}

// ---------------------------------------------------------------------------
extern "C" void kernel_launch(void* const* d_in, const int* in_sizes, int n_in,
                              void* d_out, int out_size) {
    (void)in_sizes; (void)n_in; (void)out_size;
    const float* x = (const float*)d_in[0];
    float* out = (float*)d_out;

    k_fused<<<dim3(NB, NC), 512>>>(x, out);
}